// round 1
// baseline (speedup 1.0000x reference)
#include <cuda_runtime.h>
#include <cstdint>

// Problem constants
#define B_DIM 2048
#define M_DIM 64
#define F_DIM 512
#define U_DIM 512

// Tiling
#define BM 128
#define BN 128
#define BK 16
#define TM 8
#define TN 8
#define THREADS 256   // (BM/TM)*(BN/TN)

// x: [B, M, F] row-major; for fixed mask m, X_m row stride = M*F
// W: [M, F, U];  W_m row stride = U
// out: [B, M*U]; row stride = M*U

__global__ __launch_bounds__(THREADS, 2)
void parallel_dense_sgemm(const float* __restrict__ x,
                          const float* __restrict__ W,
                          const float* __restrict__ bias,
                          float* __restrict__ out)
{
    const int bn = blockIdx.x;   // unit tile:   [0, U/BN)
    const int bm = blockIdx.y;   // batch tile:  [0, B/BM)
    const int m  = blockIdx.z;   // mask:        [0, M)

    const int tid = threadIdx.x;
    const int tx  = tid & 15;          // 0..15 -> N direction
    const int ty  = tid >> 4;          // 0..15 -> M direction

    __shared__ float As[BK][BM + 4];   // +4 pad: conflict-free transposed stores
    __shared__ float Bs[BK][BN];

    const int LDX = M_DIM * F_DIM;     // 32768
    const int LDO = M_DIM * U_DIM;     // 32768

    const float* Xm = x + (size_t)m * F_DIM;              // x[b][m][f] base
    const float* Wm = W + (size_t)m * F_DIM * U_DIM;      // W[m][f][u] base

    const int rowBase = bm * BM;       // batch row base
    const int colBase = bn * BN;       // unit col base

    float acc[TM][TN];
#pragma unroll
    for (int i = 0; i < TM; ++i)
#pragma unroll
        for (int j = 0; j < TN; ++j) acc[i][j] = 0.0f;

    // Precompute load coordinates (same every k-iter, only k0 changes)
    // A tile: BM x BK = 128x16 floats = 512 float4; 2 per thread
    const int aE0 = tid;               // float4 index 0..255
    const int aE1 = tid + 256;         // float4 index 256..511
    const int aRow0 = aE0 >> 2, aC40 = aE0 & 3;
    const int aRow1 = aE1 >> 2, aC41 = aE1 & 3;
    // B tile: BK x BN = 16x128 floats = 512 float4; 2 per thread
    const int bRow0 = aE0 >> 5, bC40 = aE0 & 31;
    const int bRow1 = aE1 >> 5, bC41 = aE1 & 31;

    const float* aPtr0 = Xm + (size_t)(rowBase + aRow0) * LDX + aC40 * 4;
    const float* aPtr1 = Xm + (size_t)(rowBase + aRow1) * LDX + aC41 * 4;
    const float* bPtr0 = Wm + (size_t)bRow0 * U_DIM + colBase + bC40 * 4;
    const float* bPtr1 = Wm + (size_t)bRow1 * U_DIM + colBase + bC41 * 4;

    for (int k0 = 0; k0 < F_DIM; k0 += BK) {
        // ---- load A tile (transposed into As[k][m]) ----
        {
            float4 v0 = *(const float4*)(aPtr0 + k0);
            float4 v1 = *(const float4*)(aPtr1 + k0);
            As[aC40 * 4 + 0][aRow0] = v0.x;
            As[aC40 * 4 + 1][aRow0] = v0.y;
            As[aC40 * 4 + 2][aRow0] = v0.z;
            As[aC40 * 4 + 3][aRow0] = v0.w;
            As[aC41 * 4 + 0][aRow1] = v1.x;
            As[aC41 * 4 + 1][aRow1] = v1.y;
            As[aC41 * 4 + 2][aRow1] = v1.z;
            As[aC41 * 4 + 3][aRow1] = v1.w;
        }
        // ---- load B tile (natural layout) ----
        {
            float4 v0 = *(const float4*)(bPtr0 + (size_t)k0 * U_DIM);
            float4 v1 = *(const float4*)(bPtr1 + (size_t)k0 * U_DIM);
            *(float4*)&Bs[bRow0][bC40 * 4] = v0;
            *(float4*)&Bs[bRow1][bC41 * 4] = v1;
        }
        __syncthreads();

        // ---- compute ----
#pragma unroll
        for (int k = 0; k < BK; ++k) {
            float af[TM], bf[TN];
#pragma unroll
            for (int i = 0; i < TM; ++i) af[i] = As[k][ty * TM + i];
#pragma unroll
            for (int j = 0; j < TN; ++j) bf[j] = Bs[k][tx * TN + j];
#pragma unroll
            for (int i = 0; i < TM; ++i)
#pragma unroll
                for (int j = 0; j < TN; ++j)
                    acc[i][j] = fmaf(af[i], bf[j], acc[i][j]);
        }
        __syncthreads();
    }

    // ---- epilogue: bias + relu + store ----
    const int row0 = rowBase + ty * TM;
    const int col0 = colBase + tx * TN;
    float bv[TN];
#pragma unroll
    for (int j = 0; j < TN; ++j) bv[j] = bias[m * U_DIM + col0 + j];

#pragma unroll
    for (int i = 0; i < TM; ++i) {
        float4 o0, o1;
        o0.x = fmaxf(acc[i][0] + bv[0], 0.0f);
        o0.y = fmaxf(acc[i][1] + bv[1], 0.0f);
        o0.z = fmaxf(acc[i][2] + bv[2], 0.0f);
        o0.w = fmaxf(acc[i][3] + bv[3], 0.0f);
        o1.x = fmaxf(acc[i][4] + bv[4], 0.0f);
        o1.y = fmaxf(acc[i][5] + bv[5], 0.0f);
        o1.z = fmaxf(acc[i][6] + bv[6], 0.0f);
        o1.w = fmaxf(acc[i][7] + bv[7], 0.0f);
        float* op = out + (size_t)(row0 + i) * LDO + m * U_DIM + col0;
        *(float4*)(op + 0) = o0;
        *(float4*)(op + 4) = o1;
    }
}

extern "C" void kernel_launch(void* const* d_in, const int* in_sizes, int n_in,
                              void* d_out, int out_size)
{
    const float* x    = (const float*)d_in[0];
    const float* W    = (const float*)d_in[1];
    const float* bias = (const float*)d_in[2];
    float* out        = (float*)d_out;

    dim3 grid(U_DIM / BN, B_DIM / BM, M_DIM);   // (4, 16, 64) = 4096 CTAs
    dim3 block(THREADS);
    parallel_dense_sgemm<<<grid, block>>>(x, W, bias, out);
}

// round 5
// speedup vs baseline: 3.0769x; 3.0769x over previous
#include <cuda_runtime.h>
#include <cstdint>

#define B_DIM 2048
#define M_DIM 64
#define F_DIM 512
#define U_DIM 512
#define LDX (M_DIM * F_DIM)
#define LDO (M_DIM * U_DIM)

#define BM 128
#define BN 128
#define BK 32
#define THREADS 256            // 8 warps: 4 (M) x 2 (N), warp tile 32x64
#define KITERS (F_DIM / BK)    // 16

// padded shared strides (floats): 36 -> conflict-free fragment gathers
#define ASTRIDE 36
#define TILE_FLOATS (128 * ASTRIDE)          // per A or B tile: 4608 floats
#define BUF_FLOATS (2 * TILE_FLOATS)         // A + B per buffer: 9216 floats
#define DYN_SMEM (2 * BUF_FLOATS * 4)        // double buffer: 73728 bytes

__device__ float g_Wt[(size_t)M_DIM * F_DIM * U_DIM];   // W^T: [m][u][k]

// ---------------- helpers ----------------
static __device__ __forceinline__ uint32_t cvta_smem(const void* p) {
    uint32_t a;
    asm("{ .reg .u64 t; cvta.to.shared.u64 t, %1; cvt.u32.u64 %0, t; }" : "=r"(a) : "l"(p));
    return a;
}
static __device__ __forceinline__ void cp_async16(uint32_t smem_addr, const void* gptr) {
    asm volatile("cp.async.cg.shared.global [%0], [%1], 16;" :: "r"(smem_addr), "l"(gptr) : "memory");
}
static __device__ __forceinline__ void cp_commit() {
    asm volatile("cp.async.commit_group;" ::: "memory");
}
template <int N>
static __device__ __forceinline__ void cp_wait() {
    asm volatile("cp.async.wait_group %0;" :: "n"(N) : "memory");
}
static __device__ __forceinline__ void mma_tf32(float* c, const uint32_t* a, const uint32_t* b) {
    asm volatile(
        "mma.sync.aligned.m16n8k8.row.col.f32.tf32.tf32.f32 "
        "{%0,%1,%2,%3}, {%4,%5,%6,%7}, {%8,%9}, {%0,%1,%2,%3};"
        : "+f"(c[0]), "+f"(c[1]), "+f"(c[2]), "+f"(c[3])
        : "r"(a[0]), "r"(a[1]), "r"(a[2]), "r"(a[3]), "r"(b[0]), "r"(b[1]));
}

// ---------------- W transpose: g_Wt[m][u][k] = W[m][k][u] ----------------
__global__ void transpose_W_kernel(const float* __restrict__ W) {
    __shared__ float t[32][33];
    const int m = blockIdx.z;
    const int u0 = blockIdx.x * 32, k0 = blockIdx.y * 32;
    const int tx = threadIdx.x, ty = threadIdx.y;
    const float* Wm = W + (size_t)m * F_DIM * U_DIM;
    float* Wtm = g_Wt + (size_t)m * F_DIM * U_DIM;
#pragma unroll
    for (int i = 0; i < 32; i += 8)
        t[ty + i][tx] = Wm[(size_t)(k0 + ty + i) * U_DIM + u0 + tx];
    __syncthreads();
#pragma unroll
    for (int i = 0; i < 32; i += 8)
        Wtm[(size_t)(u0 + ty + i) * F_DIM + k0 + tx] = t[tx][ty + i];
}

// ---------------- main GEMM: mma.sync tf32 ----------------
__global__ __launch_bounds__(THREADS)
void pd_mma_tf32(const float* __restrict__ x,
                 const float* __restrict__ bias,
                 float* __restrict__ out) {
    extern __shared__ __align__(16) float smem[];
    const uint32_t smemAddr = cvta_smem(smem);

    const int tid  = threadIdx.x;
    const int wid  = tid >> 5;
    const int lane = tid & 31;
    const int warpM = wid >> 1;         // 0..3
    const int warpN = wid & 1;          // 0..1
    const int g = lane >> 2;            // groupID
    const int t = lane & 3;             // thread-in-group

    const int bn = blockIdx.x, bm = blockIdx.y, m = blockIdx.z;
    const int rowBase = bm * BM;
    const int colBase = bn * BN;

    const float* Xm  = x + (size_t)m * F_DIM;
    const float* Wtm = g_Wt + (size_t)m * F_DIM * U_DIM;

    // staging coordinates: 128 rows x 8 float4 = 1024 chunks; 4 per thread
    const float* aSrc[4]; const float* bSrc[4];
    uint32_t dstOff[4];   // float-offset within a tile (same for A and B)
    {
#pragma unroll
        for (int j = 0; j < 4; ++j) {
            int e = j * 256 + tid;
            int r = e >> 3, c = e & 7;
            aSrc[j] = Xm  + (size_t)(rowBase + r) * LDX + c * 4;
            bSrc[j] = Wtm + (size_t)(colBase + r) * F_DIM + c * 4;
            dstOff[j] = (uint32_t)(r * ASTRIDE + c * 4);
        }
    }

    auto issue_loads = [&](int buf, int k0) {
        uint32_t base = smemAddr + (uint32_t)buf * (BUF_FLOATS * 4);
#pragma unroll
        for (int j = 0; j < 4; ++j)
            cp_async16(base + dstOff[j] * 4, aSrc[j] + k0);
#pragma unroll
        for (int j = 0; j < 4; ++j)
            cp_async16(base + (TILE_FLOATS + dstOff[j]) * 4, bSrc[j] + k0);
        cp_commit();
    };

    float acc[2][8][4];
#pragma unroll
    for (int mi = 0; mi < 2; ++mi)
#pragma unroll
        for (int ni = 0; ni < 8; ++ni)
#pragma unroll
            for (int c = 0; c < 4; ++c) acc[mi][ni][c] = 0.0f;

    // prologue
    issue_loads(0, 0);

    for (int it = 0; it < KITERS; ++it) {
        if (it + 1 < KITERS) issue_loads((it + 1) & 1, (it + 1) * BK);
        if (it + 1 < KITERS) cp_wait<1>(); else cp_wait<0>();
        __syncthreads();

        const float* As = smem + (it & 1) * BUF_FLOATS;
        const float* Bs = As + TILE_FLOATS;
        const float* aBase = As + (warpM * 32 + g) * ASTRIDE + t;
        const float* bBase = Bs + (warpN * 64 + g) * ASTRIDE + t;

#pragma unroll
        for (int ks = 0; ks < 4; ++ks) {
            const int k0 = ks * 8;
            uint32_t af[2][4], bf[8][2];
#pragma unroll
            for (int mi = 0; mi < 2; ++mi) {
                const float* p = aBase + mi * 16 * ASTRIDE + k0;
                af[mi][0] = __float_as_uint(p[0]);
                af[mi][1] = __float_as_uint(p[8 * ASTRIDE]);
                af[mi][2] = __float_as_uint(p[4]);
                af[mi][3] = __float_as_uint(p[8 * ASTRIDE + 4]);
            }
#pragma unroll
            for (int ni = 0; ni < 8; ++ni) {
                const float* p = bBase + ni * 8 * ASTRIDE + k0;
                bf[ni][0] = __float_as_uint(p[0]);
                bf[ni][1] = __float_as_uint(p[4]);
            }
#pragma unroll
            for (int mi = 0; mi < 2; ++mi)
#pragma unroll
                for (int ni = 0; ni < 8; ++ni)
                    mma_tf32(acc[mi][ni], af[mi], bf[ni]);
        }
        __syncthreads();
    }

    // ---------------- epilogue: bias + relu + store ----------------
    const float* bm_bias = bias + (size_t)m * U_DIM + colBase + warpN * 64;
#pragma unroll
    for (int mi = 0; mi < 2; ++mi) {
        const int r0 = rowBase + warpM * 32 + mi * 16 + g;
        float* o0 = out + (size_t)r0 * LDO + (size_t)m * U_DIM + colBase + warpN * 64;
        float* o1 = o0 + (size_t)8 * LDO;
#pragma unroll
        for (int ni = 0; ni < 8; ++ni) {
            const int c = ni * 8 + t * 2;
            const float b0 = bm_bias[c], b1 = bm_bias[c + 1];
            float2 v0, v1;
            v0.x = fmaxf(acc[mi][ni][0] + b0, 0.0f);
            v0.y = fmaxf(acc[mi][ni][1] + b1, 0.0f);
            v1.x = fmaxf(acc[mi][ni][2] + b0, 0.0f);
            v1.y = fmaxf(acc[mi][ni][3] + b1, 0.0f);
            *(float2*)(o0 + c) = v0;
            *(float2*)(o1 + c) = v1;
        }
    }
}

// ---------------- launch ----------------
extern "C" void kernel_launch(void* const* d_in, const int* in_sizes, int n_in,
                              void* d_out, int out_size) {
    const float* x    = (const float*)d_in[0];
    const float* W    = (const float*)d_in[1];
    const float* bias = (const float*)d_in[2];
    float* out        = (float*)d_out;

    dim3 tg(U_DIM / 32, F_DIM / 32, M_DIM);   // (16,16,64)
    transpose_W_kernel<<<tg, dim3(32, 8)>>>(W);

    cudaFuncSetAttribute(pd_mma_tf32, cudaFuncAttributeMaxDynamicSharedMemorySize, DYN_SMEM);
    dim3 grid(U_DIM / BN, B_DIM / BM, M_DIM);  // (4,16,64) = 4096 CTAs
    pd_mma_tf32<<<grid, THREADS, DYN_SMEM>>>(x, bias, out);
}

// round 7
// speedup vs baseline: 3.5166x; 1.1429x over previous
#include <cuda_runtime.h>
#include <cstdint>

#define B_DIM 2048
#define M_DIM 64
#define F_DIM 512
#define U_DIM 512
#define LDX (M_DIM * F_DIM)
#define LDO (M_DIM * U_DIM)

#define BM 128
#define BN 128
#define BK 32
#define THREADS 256            // 8 warps: 4 (M) x 2 (N), warp tile 32x64
#define KITERS (F_DIM / BK)    // 16

#define ASTRIDE 36                           // floats; conflict-free for LDSM + frag reads
#define TILE_BYTES (128 * ASTRIDE * 4)       // 18432 B per A or B tile
#define STAGE_BYTES (2 * TILE_BYTES)         // 36864 B
#define STAGES 3
#define DYN_SMEM (STAGES * STAGE_BYTES)      // 110592 B -> 2 CTAs/SM

__device__ float g_Wt[(size_t)M_DIM * F_DIM * U_DIM];   // W^T (tf32-rounded): [m][u][k]

// ---------------- helpers ----------------
static __device__ __forceinline__ uint32_t cvta_smem(const void* p) {
    uint32_t a;
    asm("{ .reg .u64 t; cvta.to.shared.u64 t, %1; cvt.u32.u64 %0, t; }" : "=r"(a) : "l"(p));
    return a;
}
static __device__ __forceinline__ void cp_async16(uint32_t smem_addr, const void* gptr) {
    asm volatile("cp.async.cg.shared.global [%0], [%1], 16;" :: "r"(smem_addr), "l"(gptr) : "memory");
}
static __device__ __forceinline__ void cp_commit() {
    asm volatile("cp.async.commit_group;" ::: "memory");
}
template <int N>
static __device__ __forceinline__ void cp_wait() {
    asm volatile("cp.async.wait_group %0;" :: "n"(N) : "memory");
}
static __device__ __forceinline__ void ldsm_x4(uint32_t addr, uint32_t* r) {
    asm volatile("ldmatrix.sync.aligned.m8n8.x4.shared.b16 {%0,%1,%2,%3}, [%4];"
                 : "=r"(r[0]), "=r"(r[1]), "=r"(r[2]), "=r"(r[3]) : "r"(addr));
}
static __device__ __forceinline__ void mma_tf32(float* c, const uint32_t* a, const uint32_t* b) {
    asm volatile(
        "mma.sync.aligned.m16n8k8.row.col.f32.tf32.tf32.f32 "
        "{%0,%1,%2,%3}, {%4,%5,%6,%7}, {%8,%9}, {%0,%1,%2,%3};"
        : "+f"(c[0]), "+f"(c[1]), "+f"(c[2]), "+f"(c[3])
        : "r"(a[0]), "r"(a[1]), "r"(a[2]), "r"(a[3]), "r"(b[0]), "r"(b[1]));
}
static __device__ __forceinline__ float f2tf32_rn(float f) {
    uint32_t u; asm("cvt.rn.tf32.f32 %0, %1;" : "=r"(u) : "f"(f));
    return __uint_as_float(u);
}

// ---------------- W transpose + tf32 round: g_Wt[m][u][k] = tf32(W[m][k][u]) ----------------
__global__ void transpose_W_kernel(const float* __restrict__ W) {
    __shared__ float t[32][33];
    const int m = blockIdx.z;
    const int u0 = blockIdx.x * 32, k0 = blockIdx.y * 32;
    const int tx = threadIdx.x, ty = threadIdx.y;
    const float* Wm = W + (size_t)m * F_DIM * U_DIM;
    float* Wtm = g_Wt + (size_t)m * F_DIM * U_DIM;
#pragma unroll
    for (int i = 0; i < 32; i += 8)
        t[ty + i][tx] = f2tf32_rn(Wm[(size_t)(k0 + ty + i) * U_DIM + u0 + tx]);
    __syncthreads();
#pragma unroll
    for (int i = 0; i < 32; i += 8)
        Wtm[(size_t)(u0 + ty + i) * F_DIM + k0 + tx] = t[tx][ty + i];
}

// ---------------- main GEMM: mma.sync tf32, ldmatrix feeds, 3-stage cp.async ----------------
__global__ __launch_bounds__(THREADS, 2)
void pd_mma_tf32(const float* __restrict__ x,
                 const float* __restrict__ bias,
                 float* __restrict__ out) {
    extern __shared__ __align__(16) float smem[];
    const uint32_t smemAddr = cvta_smem(smem);

    const int tid  = threadIdx.x;
    const int wid  = tid >> 5;
    const int lane = tid & 31;
    const int warpM = wid >> 1;         // 0..3
    const int warpN = wid & 1;          // 0..1
    const int g = lane >> 2;            // groupID
    const int t = lane & 3;             // thread-in-group
    const int quad = lane >> 3;         // ldmatrix address quad
    const int rl   = lane & 7;

    const int bn = blockIdx.x, bm = blockIdx.y, m = blockIdx.z;
    const int rowBase = bm * BM;
    const int colBase = bn * BN;

    const float* Xm  = x + (size_t)m * F_DIM;
    const float* Wtm = g_Wt + (size_t)m * F_DIM * U_DIM;

    // ---- staging coordinates: 128 rows x 8 float4 chunks per tile; 4 per thread ----
    const float* aSrc[4]; const float* bSrc[4];
    uint32_t dstOff[4];
#pragma unroll
    for (int j = 0; j < 4; ++j) {
        int e = j * 256 + tid;
        int r = e >> 3, c = e & 7;
        aSrc[j] = Xm  + (size_t)(rowBase + r) * LDX + c * 4;
        bSrc[j] = Wtm + (size_t)(colBase + r) * F_DIM + c * 4;
        dstOff[j] = (uint32_t)(r * ASTRIDE + c * 4) * 4;
    }

    auto issue_loads = [&](uint32_t stageOff, int k0) {
        uint32_t base = smemAddr + stageOff;
#pragma unroll
        for (int j = 0; j < 4; ++j)
            cp_async16(base + dstOff[j], aSrc[j] + k0);
#pragma unroll
        for (int j = 0; j < 4; ++j)
            cp_async16(base + TILE_BYTES + dstOff[j], bSrc[j] + k0);
        cp_commit();
    };

    // ---- ldmatrix per-lane address offsets (within a stage) ----
    // A x4 tiles: [rows mBase+0-7, k0-3][rows +8-15, k0-3][rows 0-7, k4-7][rows 8-15, k4-7]
    const uint32_t aLaneOff =
        (uint32_t)(((warpM * 32 + (quad & 1) * 8 + rl) * ASTRIDE + (quad >> 1) * 4) * 4);
    // B x4 tiles: [rows nBase+0-7, k0-3][rows 0-7, k4-7][rows +8-15, k0-3][rows 8-15, k4-7]
    const uint32_t bLaneOff =
        (uint32_t)(((warpN * 64 + (quad >> 1) * 8 + rl) * ASTRIDE + (quad & 1) * 4) * 4) + TILE_BYTES;

    float acc[2][8][4];
#pragma unroll
    for (int mi = 0; mi < 2; ++mi)
#pragma unroll
        for (int ni = 0; ni < 8; ++ni)
#pragma unroll
            for (int c = 0; c < 4; ++c) acc[mi][ni][c] = 0.0f;

    // ---- prologue: 2 stages in flight ----
    issue_loads(0, 0);
    issue_loads(STAGE_BYTES, BK);

    uint32_t compOff  = 0;                    // stage being computed
    uint32_t issueOff = 2 * STAGE_BYTES;      // stage to fill next

    for (int it = 0; it < KITERS; ++it) {
        // Pending groups at this point: stages `it` and `it+1`.
        // wait<1> -> stage `it` fully arrived (stage `it+1` may still fly).
        cp_wait<1>();
        // Barrier: (a) stage `it` visible to all warps; (b) every warp has
        // finished computing stage `it-1`, so overwriting its buffer
        // ((it+2)%3 == (it-1)%3) below is safe.
        __syncthreads();

        if (it + 2 < KITERS) {
            issue_loads(issueOff, (it + 2) * BK);
        } else {
            cp_commit();         // keep one-group-per-iter accounting aligned
        }

        const uint32_t aA = smemAddr + compOff + aLaneOff;
        const uint32_t bA = smemAddr + compOff + bLaneOff;

#pragma unroll
        for (int ks = 0; ks < 4; ++ks) {
            uint32_t af[2][4], bf[4][4];
            ldsm_x4(aA + ks * 32,        af[0]);
            ldsm_x4(aA + 2304 + ks * 32, af[1]);            // +16 rows * 144B
#pragma unroll
            for (int p = 0; p < 4; ++p)
                ldsm_x4(bA + p * 2304 + ks * 32, bf[p]);    // 16-n pair p
#pragma unroll
            for (int mi = 0; mi < 2; ++mi)
#pragma unroll
                for (int p = 0; p < 4; ++p) {
                    mma_tf32(acc[mi][2 * p],     af[mi], &bf[p][0]);
                    mma_tf32(acc[mi][2 * p + 1], af[mi], &bf[p][2]);
                }
        }

        compOff += STAGE_BYTES;  if (compOff  == DYN_SMEM) compOff  = 0;
        issueOff += STAGE_BYTES; if (issueOff == DYN_SMEM) issueOff = 0;
    }

    // ---------------- epilogue: bias + relu + store ----------------
    const float* bm_bias = bias + (size_t)m * U_DIM + colBase + warpN * 64;
#pragma unroll
    for (int mi = 0; mi < 2; ++mi) {
        const int r0 = rowBase + warpM * 32 + mi * 16 + g;
        float* o0 = out + (size_t)r0 * LDO + (size_t)m * U_DIM + colBase + warpN * 64;
        float* o1 = o0 + (size_t)8 * LDO;
#pragma unroll
        for (int ni = 0; ni < 8; ++ni) {
            const int c = ni * 8 + t * 2;
            const float b0 = bm_bias[c], b1 = bm_bias[c + 1];
            float2 v0, v1;
            v0.x = fmaxf(acc[mi][ni][0] + b0, 0.0f);
            v0.y = fmaxf(acc[mi][ni][1] + b1, 0.0f);
            v1.x = fmaxf(acc[mi][ni][2] + b0, 0.0f);
            v1.y = fmaxf(acc[mi][ni][3] + b1, 0.0f);
            *(float2*)(o0 + c) = v0;
            *(float2*)(o1 + c) = v1;
        }
    }
}

// ---------------- launch ----------------
extern "C" void kernel_launch(void* const* d_in, const int* in_sizes, int n_in,
                              void* d_out, int out_size) {
    const float* x    = (const float*)d_in[0];
    const float* W    = (const float*)d_in[1];
    const float* bias = (const float*)d_in[2];
    float* out        = (float*)d_out;

    dim3 tg(U_DIM / 32, F_DIM / 32, M_DIM);   // (16,16,64)
    transpose_W_kernel<<<tg, dim3(32, 8)>>>(W);

    cudaFuncSetAttribute(pd_mma_tf32, cudaFuncAttributeMaxDynamicSharedMemorySize, DYN_SMEM);
    dim3 grid(U_DIM / BN, B_DIM / BM, M_DIM);  // (4,16,64) = 4096 CTAs
    pd_mma_tf32<<<grid, THREADS, DYN_SMEM>>>(x, bias, out);
}

// round 8
// speedup vs baseline: 3.6461x; 1.0368x over previous
#include <cuda_runtime.h>
#include <cstdint>

#define B_DIM 2048
#define M_DIM 64
#define F_DIM 512
#define U_DIM 512
#define LDX (M_DIM * F_DIM)
#define LDO (M_DIM * U_DIM)

#define BM 128
#define BN 128
#define BK 32
#define THREADS 256            // 8 warps: 4 (M) x 2 (N), warp tile 32x64
#define KITERS (F_DIM / BK)    // 16

#define ASTRIDE 36                           // floats; conflict-free for LDSM + frag reads
#define TILE_BYTES (128 * ASTRIDE * 4)       // 18432 B per A or B tile
#define STAGE_BYTES (2 * TILE_BYTES)         // 36864 B
#define STAGES 3
#define DYN_SMEM (STAGES * STAGE_BYTES)      // 110592 B -> 2 CTAs/SM

__device__ float g_Wt[(size_t)M_DIM * F_DIM * U_DIM];   // W^T (tf32-rounded): [m][u][k]

// ---------------- helpers ----------------
static __device__ __forceinline__ uint32_t cvta_smem(const void* p) {
    uint32_t a;
    asm("{ .reg .u64 t; cvta.to.shared.u64 t, %1; cvt.u32.u64 %0, t; }" : "=r"(a) : "l"(p));
    return a;
}
static __device__ __forceinline__ void cp_async16(uint32_t smem_addr, const void* gptr) {
    asm volatile("cp.async.cg.shared.global [%0], [%1], 16;" :: "r"(smem_addr), "l"(gptr) : "memory");
}
static __device__ __forceinline__ void cp_commit() {
    asm volatile("cp.async.commit_group;" ::: "memory");
}
template <int N>
static __device__ __forceinline__ void cp_wait() {
    asm volatile("cp.async.wait_group %0;" :: "n"(N) : "memory");
}
static __device__ __forceinline__ void ldsm_x4(uint32_t addr, uint32_t* r) {
    asm volatile("ldmatrix.sync.aligned.m8n8.x4.shared.b16 {%0,%1,%2,%3}, [%4];"
                 : "=r"(r[0]), "=r"(r[1]), "=r"(r[2]), "=r"(r[3]) : "r"(addr));
}
static __device__ __forceinline__ void mma_tf32(float* c, const uint32_t* a, const uint32_t* b) {
    asm volatile(
        "mma.sync.aligned.m16n8k8.row.col.f32.tf32.tf32.f32 "
        "{%0,%1,%2,%3}, {%4,%5,%6,%7}, {%8,%9}, {%0,%1,%2,%3};"
        : "+f"(c[0]), "+f"(c[1]), "+f"(c[2]), "+f"(c[3])
        : "r"(a[0]), "r"(a[1]), "r"(a[2]), "r"(a[3]), "r"(b[0]), "r"(b[1]));
}
static __device__ __forceinline__ float f2tf32_rn(float f) {
    uint32_t u; asm("cvt.rn.tf32.f32 %0, %1;" : "=r"(u) : "f"(f));
    return __uint_as_float(u);
}

// ---------------- W transpose + tf32 round: g_Wt[m][u][k] = tf32(W[m][k][u]) ----------------
__global__ void transpose_W_kernel(const float* __restrict__ W) {
    __shared__ float t[32][33];
    const int m = blockIdx.z;
    const int u0 = blockIdx.x * 32, k0 = blockIdx.y * 32;
    const int tx = threadIdx.x, ty = threadIdx.y;
    const float* Wm = W + (size_t)m * F_DIM * U_DIM;
    float* Wtm = g_Wt + (size_t)m * F_DIM * U_DIM;
#pragma unroll
    for (int i = 0; i < 32; i += 8)
        t[ty + i][tx] = f2tf32_rn(Wm[(size_t)(k0 + ty + i) * U_DIM + u0 + tx]);
    __syncthreads();
#pragma unroll
    for (int i = 0; i < 32; i += 8)
        Wtm[(size_t)(u0 + ty + i) * F_DIM + k0 + tx] = t[tx][ty + i];
}

// ---------------- main GEMM: mma.sync tf32, ldmatrix feeds, 3-stage cp.async ----------------
__global__ __launch_bounds__(THREADS, 2)
void pd_mma_tf32(const float* __restrict__ x,
                 const float* __restrict__ bias,
                 float* __restrict__ out) {
    extern __shared__ __align__(16) float smem[];
    const uint32_t smemAddr = cvta_smem(smem);

    const int tid  = threadIdx.x;
    const int wid  = tid >> 5;
    const int lane = tid & 31;
    const int warpM = wid >> 1;         // 0..3
    const int warpN = wid & 1;          // 0..1
    const int g = lane >> 2;            // groupID
    const int t = lane & 3;             // thread-in-group
    const int quad = lane >> 3;         // ldmatrix address quad
    const int rl   = lane & 7;
    const int rot  = (wid & 1) * 2;     // ks start offset: desync LDSM bursts

    const int bn = blockIdx.x, bm = blockIdx.y, m = blockIdx.z;
    const int rowBase = bm * BM;
    const int colBase = bn * BN;

    const float* Xm  = x + (size_t)m * F_DIM;
    const float* Wtm = g_Wt + (size_t)m * F_DIM * U_DIM;

    // ---- staging coordinates: 128 rows x 8 float4 chunks per tile; 4 per thread ----
    const float* aSrc[4]; const float* bSrc[4];
    uint32_t dstOff[4];
#pragma unroll
    for (int j = 0; j < 4; ++j) {
        int e = j * 256 + tid;
        int r = e >> 3, c = e & 7;
        aSrc[j] = Xm  + (size_t)(rowBase + r) * LDX + c * 4;
        bSrc[j] = Wtm + (size_t)(colBase + r) * F_DIM + c * 4;
        dstOff[j] = (uint32_t)(r * ASTRIDE + c * 4) * 4;
    }

    auto issue_loads = [&](uint32_t stageOff, int k0) {
        uint32_t base = smemAddr + stageOff;
#pragma unroll
        for (int j = 0; j < 4; ++j)
            cp_async16(base + dstOff[j], aSrc[j] + k0);
#pragma unroll
        for (int j = 0; j < 4; ++j)
            cp_async16(base + TILE_BYTES + dstOff[j], bSrc[j] + k0);
        cp_commit();
    };

    // ---- ldmatrix per-lane address offsets (within a stage) ----
    // A x4 tiles: [rows mBase+0-7, k0-3][rows +8-15, k0-3][rows 0-7, k4-7][rows 8-15, k4-7]
    const uint32_t aLaneOff =
        (uint32_t)(((warpM * 32 + (quad & 1) * 8 + rl) * ASTRIDE + (quad >> 1) * 4) * 4);
    // B x4 tiles: [rows nBase+0-7, k0-3][rows 0-7, k4-7][rows +8-15, k0-3][rows 8-15, k4-7]
    const uint32_t bLaneOff =
        (uint32_t)(((warpN * 64 + (quad >> 1) * 8 + rl) * ASTRIDE + (quad & 1) * 4) * 4) + TILE_BYTES;

    float acc[2][8][4];
#pragma unroll
    for (int mi = 0; mi < 2; ++mi)
#pragma unroll
        for (int ni = 0; ni < 8; ++ni)
#pragma unroll
            for (int c = 0; c < 4; ++c) acc[mi][ni][c] = 0.0f;

    // ---- prologue: 2 stages in flight ----
    issue_loads(0, 0);
    issue_loads(STAGE_BYTES, BK);

    uint32_t compOff  = 0;                    // stage being computed
    uint32_t issueOff = 2 * STAGE_BYTES;      // stage to fill next

    for (int it = 0; it < KITERS; ++it) {
        // Pending groups: stages `it`, `it+1`. wait<1> -> stage `it` arrived.
        cp_wait<1>();
        // Barrier: stage `it` visible; all warps done with stage `it-1`
        // (whose buffer is re-filled below).
        __syncthreads();

        const uint32_t aA = smemAddr + compOff + aLaneOff;
        const uint32_t bA = smemAddr + compOff + bLaneOff;

#pragma unroll
        for (int kk = 0; kk < 4; ++kk) {
            const int ks = (kk + rot) & 3;     // warp-parity rotated k-chunk
            const uint32_t ko = (uint32_t)(ks * 32);

            uint32_t af[2][4], bf[4][4];
            // A frags + first B pair
            ldsm_x4(aA + ko,        af[0]);
            ldsm_x4(aA + 2304 + ko, af[1]);            // +16 rows * 144B
            ldsm_x4(bA + ko,        bf[0]);
            ldsm_x4(bA + 2304 + ko, bf[1]);
            // MMAs for p=0,1 while bf[2..3] load
#pragma unroll
            for (int p = 0; p < 2; ++p) {
#pragma unroll
                for (int mi = 0; mi < 2; ++mi) {
                    mma_tf32(acc[mi][2 * p],     af[mi], &bf[p][0]);
                    mma_tf32(acc[mi][2 * p + 1], af[mi], &bf[p][2]);
                }
            }
            ldsm_x4(bA + 2 * 2304 + ko, bf[2]);
            ldsm_x4(bA + 3 * 2304 + ko, bf[3]);

            // Defer cp.async issue out of the post-barrier LDSM window
            if (kk == 0) {
                if (it + 2 < KITERS) issue_loads(issueOff, (it + 2) * BK);
                else                 cp_commit();   // keep group accounting aligned
            }

#pragma unroll
            for (int p = 2; p < 4; ++p) {
#pragma unroll
                for (int mi = 0; mi < 2; ++mi) {
                    mma_tf32(acc[mi][2 * p],     af[mi], &bf[p][0]);
                    mma_tf32(acc[mi][2 * p + 1], af[mi], &bf[p][2]);
                }
            }
        }

        compOff += STAGE_BYTES;  if (compOff  == DYN_SMEM) compOff  = 0;
        issueOff += STAGE_BYTES; if (issueOff == DYN_SMEM) issueOff = 0;
    }

    // ---------------- epilogue: bias + relu + store ----------------
    const float* bm_bias = bias + (size_t)m * U_DIM + colBase + warpN * 64;
#pragma unroll
    for (int mi = 0; mi < 2; ++mi) {
        const int r0 = rowBase + warpM * 32 + mi * 16 + g;
        float* o0 = out + (size_t)r0 * LDO + (size_t)m * U_DIM + colBase + warpN * 64;
        float* o1 = o0 + (size_t)8 * LDO;
#pragma unroll
        for (int ni = 0; ni < 8; ++ni) {
            const int c = ni * 8 + t * 2;
            const float b0 = bm_bias[c], b1 = bm_bias[c + 1];
            float2 v0, v1;
            v0.x = fmaxf(acc[mi][ni][0] + b0, 0.0f);
            v0.y = fmaxf(acc[mi][ni][1] + b1, 0.0f);
            v1.x = fmaxf(acc[mi][ni][2] + b0, 0.0f);
            v1.y = fmaxf(acc[mi][ni][3] + b1, 0.0f);
            *(float2*)(o0 + c) = v0;
            *(float2*)(o1 + c) = v1;
        }
    }
}

// ---------------- launch ----------------
extern "C" void kernel_launch(void* const* d_in, const int* in_sizes, int n_in,
                              void* d_out, int out_size) {
    const float* x    = (const float*)d_in[0];
    const float* W    = (const float*)d_in[1];
    const float* bias = (const float*)d_in[2];
    float* out        = (float*)d_out;

    dim3 tg(U_DIM / 32, F_DIM / 32, M_DIM);   // (16,16,64)
    transpose_W_kernel<<<tg, dim3(32, 8)>>>(W);

    cudaFuncSetAttribute(pd_mma_tf32, cudaFuncAttributeMaxDynamicSharedMemorySize, DYN_SMEM);
    dim3 grid(U_DIM / BN, B_DIM / BM, M_DIM);  // (4,16,64) = 4096 CTAs
    pd_mma_tf32<<<grid, THREADS, DYN_SMEM>>>(x, bias, out);
}